// round 2
// baseline (speedup 1.0000x reference)
#include <cuda_runtime.h>
#include <cuda_bf16.h>

// BasicLSTM: SEQ=512, BATCH=64, HID=1024, LAYERS=2
// gates = [x, h] @ W[l] + b[l];  i,j,f,o = split(gates,4)
// c' = c*sig(f) + sig(i)*tanh(j);  h' = tanh(c')*sig(o)
//
// Round 2: ONE persistent kernel (single graph node -> no graph-upload leak).
// 128 co-resident blocks, software grid barrier, split-K FFMA2 GEMM with
// ping-pong SMEM double buffering, fused cell phase.

#define SEQ    512
#define BATCH  64
#define HID    1024
#define HID2   2048
#define HID4   4096
#define BH     (BATCH * HID)          // 65536
#define GATES  (BATCH * HID4)         // 262144
#define NSLICE 8                      // K split factor (2048/256)
#define NBLK   128                    // 16 col groups x 8 k slices
#define NTHR   256

// ---------------- device scratch (no allocs allowed) ----------------
__device__ float g_partial[NSLICE][GATES];   // 8 MB split-K partial gate sums
__device__ float g_h[2][2][BH];              // [parity][layer][b*H+m]
__device__ float g_c[2][BH];                 // [layer][b*H+m]
__device__ unsigned g_bar_arrive;            // zero-initialized
__device__ unsigned g_bar_gen;

// ---------------- packed f32x2 FMA (Blackwell FFMA2) ----------------
__device__ __forceinline__ void ffma2(unsigned long long& d,
                                      unsigned long long a,
                                      unsigned long long b) {
    asm("fma.rn.f32x2 %0, %1, %2, %0;" : "+l"(d) : "l"(a), "l"(b));
}

__device__ __forceinline__ float sigmoidf_(float x) {
    return 1.0f / (1.0f + expf(-x));
}

// ---------------- software grid barrier (all NBLK blocks resident) -------
__device__ __forceinline__ void grid_barrier() {
    __syncthreads();
    if (threadIdx.x == 0) {
        __threadfence();                               // release prior writes
        unsigned gen = *((volatile unsigned*)&g_bar_gen);
        if (atomicAdd(&g_bar_arrive, 1u) == NBLK - 1) {
            g_bar_arrive = 0;
            __threadfence();
            atomicAdd(&g_bar_gen, 1u);                 // release all waiters
        } else {
            while (*((volatile unsigned*)&g_bar_gen) == gen) { __nanosleep(32); }
        }
        __threadfence();                               // acquire
    }
    __syncthreads();
}

// ---------------- GEMM phase: partial[ks] = A[:,kslice] @ W[kslice, n0:+256]
__device__ __forceinline__ void gemm_phase(
    const float* __restrict__ xpart,   // [64,1024], k in [0,1024)
    const float* __restrict__ hpart,   // [64,1024], k in [1024,2048)
    const float* __restrict__ Wl,      // [2048,4096]
    int cg, int ks, int tid,
    float2 (&sA)[2][16][64], float (&sW)[2][16][256])
{
    const float* src;
    int kofs;
    if (ks < 4) { src = xpart; kofs = ks * 256; }
    else        { src = hpart; kofs = (ks - 4) * 256; }
    const int kW = ks * 256;
    const int n0 = cg * 256;

    const int la_b  = tid >> 2;            // 0..63
    const int la_kq = (tid & 3) * 4;       // {0,4,8,12}
    const int lw_kr = tid >> 4;            // 0..15
    const int lw_nq = tid & 15;            // 0..15

    const int warp = tid >> 5;
    const int lane = tid & 31;
    const int b0   = warp * 8;
    const int nl   = lane * 8;

    const float* aptr = src + la_b * HID + kofs + la_kq;
    const float* wptr = Wl + (size_t)(kW + lw_kr) * HID4 + n0 + lw_nq * 16;

    // prefetch tile 0
    float4 va = *reinterpret_cast<const float4*>(aptr);
    float4 vw[4];
#pragma unroll
    for (int c = 0; c < 4; c++)
        vw[c] = *reinterpret_cast<const float4*>(wptr + c * 4);

    unsigned long long acc[8][4];
#pragma unroll
    for (int i = 0; i < 8; i++)
#pragma unroll
        for (int j = 0; j < 4; j++) acc[i][j] = 0ull;

    for (int kt = 0; kt < 16; kt++) {
        const int buf = kt & 1;

        // store prefetched tile to smem (A duplicated pairs, transposed)
        sA[buf][la_kq + 0][la_b] = make_float2(va.x, va.x);
        sA[buf][la_kq + 1][la_b] = make_float2(va.y, va.y);
        sA[buf][la_kq + 2][la_b] = make_float2(va.z, va.z);
        sA[buf][la_kq + 3][la_b] = make_float2(va.w, va.w);
#pragma unroll
        for (int c = 0; c < 4; c++)
            *reinterpret_cast<float4*>(&sW[buf][lw_kr][lw_nq * 16 + c * 4]) = vw[c];
        __syncthreads();

        // prefetch next tile (overlaps with FFMA2 compute below)
        if (kt < 15) {
            aptr += 16;
            wptr += (size_t)16 * HID4;
            va = *reinterpret_cast<const float4*>(aptr);
#pragma unroll
            for (int c = 0; c < 4; c++)
                vw[c] = *reinterpret_cast<const float4*>(wptr + c * 4);
        }

#pragma unroll
        for (int kk = 0; kk < 16; kk++) {
            const ulonglong2* aR = reinterpret_cast<const ulonglong2*>(&sA[buf][kk][b0]);
            const ulonglong2* wR = reinterpret_cast<const ulonglong2*>(&sW[buf][kk][nl]);
            ulonglong2 a01 = aR[0], a23 = aR[1], a45 = aR[2], a67 = aR[3];
            ulonglong2 w01 = wR[0], w23 = wR[1];
            unsigned long long a[8] = {a01.x, a01.y, a23.x, a23.y,
                                       a45.x, a45.y, a67.x, a67.y};
            unsigned long long w[4] = {w01.x, w01.y, w23.x, w23.y};
#pragma unroll
            for (int i = 0; i < 8; i++)
#pragma unroll
                for (int j = 0; j < 4; j++)
                    ffma2(acc[i][j], a[i], w[j]);
        }
        // next iteration's stores go to the other buffer; the single
        // __syncthreads above is sufficient with ping-pong buffering.
    }

    // write partials (exclusive region per (cg,ks))
    float* base = &g_partial[ks][0] + n0 + nl;
#pragma unroll
    for (int i = 0; i < 8; i++) {
        ulonglong2* d = reinterpret_cast<ulonglong2*>(base + (size_t)(b0 + i) * HID4);
        d[0] = make_ulonglong2(acc[i][0], acc[i][1]);
        d[1] = make_ulonglong2(acc[i][2], acc[i][3]);
    }
}

// ---------------- cell phase: reduce partials + bias + LSTM pointwise ----
__device__ __forceinline__ void cell_phase(
    int gid,
    const float* __restrict__ bias_l,   // [4096]
    float* __restrict__ c_l,            // [BH] in-place
    float* __restrict__ h_out,          // [BH]
    float* __restrict__ out_opt)        // nullable [BH]
{
    const int idx = gid * 2;            // two consecutive elements
    const int b = idx >> 10;
    const int m = idx & 1023;

    float2 g[4];
#pragma unroll
    for (int gate = 0; gate < 4; gate++) {
        const int n = gate * 1024 + m;
        float2 s = *reinterpret_cast<const float2*>(bias_l + n);
#pragma unroll
        for (int s8 = 0; s8 < NSLICE; s8++) {
            float2 v = *reinterpret_cast<const float2*>(
                &g_partial[s8][(size_t)b * HID4 + n]);
            s.x += v.x; s.y += v.y;
        }
        g[gate] = s;
    }
    const float2 cold = *reinterpret_cast<const float2*>(c_l + idx);

    float2 cn, hn;
    {
        const float gi = sigmoidf_(g[0].x), gj = tanhf(g[1].x);
        const float gf = sigmoidf_(g[2].x), go = sigmoidf_(g[3].x);
        cn.x = cold.x * gf + gi * gj;
        hn.x = tanhf(cn.x) * go;
    }
    {
        const float gi = sigmoidf_(g[0].y), gj = tanhf(g[1].y);
        const float gf = sigmoidf_(g[2].y), go = sigmoidf_(g[3].y);
        cn.y = cold.y * gf + gi * gj;
        hn.y = tanhf(cn.y) * go;
    }
    *reinterpret_cast<float2*>(c_l + idx) = cn;
    *reinterpret_cast<float2*>(h_out + idx) = hn;
    if (out_opt) *reinterpret_cast<float2*>(out_opt + idx) = hn;
}

// ---------------- persistent kernel ----------------
__global__ void __launch_bounds__(NTHR, 1)
lstm_persistent(const float* __restrict__ input,  // [512,64,1024]
                const float* __restrict__ h0,     // [2,64,1024]
                const float* __restrict__ c0,     // [2,64,1024]
                const float* __restrict__ W,      // [2,2048,4096]
                const float* __restrict__ bias,   // [2,4096]
                float* __restrict__ out)          // [512*BH + 4*BH]
{
    __shared__ float2 sA[2][16][64];    // 16 KB
    __shared__ float  sW[2][16][256];   // 32 KB

    const int tid = threadIdx.x;
    const int bid = blockIdx.x;
    const int gid = bid * NTHR + tid;   // 0..32767
    const int cg  = bid & 15;
    const int ks  = bid >> 4;

    // ---- seed state: h0 -> g_h[0], c0 -> g_c ----
    {
        const float4* s1 = reinterpret_cast<const float4*>(h0);
        const float4* s2 = reinterpret_cast<const float4*>(c0);
        float4* d1 = reinterpret_cast<float4*>(&g_h[0][0][0]);
        float4* d2 = reinterpret_cast<float4*>(&g_c[0][0]);
        for (int i = gid; i < 2 * BH / 4; i += NBLK * NTHR) {
            d1[i] = s1[i];
            d2[i] = s2[i];
        }
    }
    grid_barrier();

    for (int t = 0; t < SEQ; t++) {
        const int pin  = t & 1;
        const int pout = pin ^ 1;

        // ---------- layer 0 ----------
        gemm_phase(input + (size_t)t * BH,      // x
                   &g_h[pin][0][0],             // h_prev layer 0
                   W, cg, ks, tid, sA, sW);
        grid_barrier();
        cell_phase(gid, bias,
                   &g_c[0][0],
                   &g_h[pout][0][0],
                   nullptr);
        grid_barrier();

        // ---------- layer 1 ----------
        gemm_phase(&g_h[pout][0][0],            // x = new h of layer 0
                   &g_h[pin][1][0],             // h_prev layer 1
                   W + (size_t)HID2 * HID4, cg, ks, tid, sA, sW);
        grid_barrier();
        cell_phase(gid, bias + HID4,
                   &g_c[1][0],
                   &g_h[pout][1][0],
                   out + (size_t)t * BH);       // final_output[t]
        grid_barrier();
    }

    // ---- tail: last_hidden (parity 0 after t=511) then last_cell ----
    {
        float* tail = out + (size_t)SEQ * BH;
        const float4* hs = reinterpret_cast<const float4*>(&g_h[0][0][0]);
        const float4* cs = reinterpret_cast<const float4*>(&g_c[0][0]);
        float4* dh = reinterpret_cast<float4*>(tail);
        float4* dc = reinterpret_cast<float4*>(tail + 2 * BH);
        for (int i = gid; i < 2 * BH / 4; i += NBLK * NTHR) {
            dh[i] = hs[i];
            dc[i] = cs[i];
        }
    }
}

// ---------------- launch: ONE graph node ----------------
extern "C" void kernel_launch(void* const* d_in, const int* in_sizes, int n_in,
                              void* d_out, int out_size) {
    const float* input = (const float*)d_in[0];
    const float* h0    = (const float*)d_in[1];
    const float* c0    = (const float*)d_in[2];
    const float* W     = (const float*)d_in[3];
    const float* bias  = (const float*)d_in[4];
    float* out = (float*)d_out;

    lstm_persistent<<<NBLK, NTHR>>>(input, h0, c0, W, bias, out);
}

// round 5
// speedup vs baseline: 2.6947x; 2.6947x over previous
#include <cuda_runtime.h>
#include <cuda_bf16.h>
#include <cstdint>

// BasicLSTM via mma.sync (HMMA bf16, 3-term fp32-split emulation).
// SEQ=512, BATCH=64, HID=1024, LAYERS=2.
// One persistent kernel, 128 CTAs (32 M-tiles x 4 K-slices), grid barriers.
// R5 fix: per-access swizzle (col XOR applied to final column, no post-swizzle add).

#define SEQ    512
#define BATCH  64
#define HID    1024
#define KTOT   2048
#define NOUT   4096
#define BH     (BATCH * HID)        // 65536
#define NBLK   128
#define NTHR   256
#define GTH    (NBLK * NTHR)
#define NKS    4
#define KSL    512                  // K per slice
#define CHK    64                   // K per chunk
#define NCHK   (KSL / CHK)          // 8
#define STGB   49152                // Ahi16K | Alo16K | Bhi8K | Blo8K
#define DSMEM  (2 * STGB)

// ---------------- device globals (no allocs) ----------------
// activations stored [feature k][batch b] (k-major) for ldmatrix.trans
__device__ __align__(128) __nv_bfloat16 g_xhi[(size_t)SEQ * HID * 64];
__device__ __align__(128) __nv_bfloat16 g_xlo[(size_t)SEQ * HID * 64];
__device__ __align__(128) __nv_bfloat16 g_wthi[(size_t)2 * NOUT * KTOT]; // [l][p][k]
__device__ __align__(128) __nv_bfloat16 g_wtlo[(size_t)2 * NOUT * KTOT];
__device__ __align__(128) __nv_bfloat16 g_hhi[4 * BH];   // [par*2+l][u][b]
__device__ __align__(128) __nv_bfloat16 g_hlo[4 * BH];
__device__ __align__(128) float g_partial[(size_t)NKS * NOUT * 64]; // [ks][p][b]
__device__ __align__(128) float g_c[2 * BH];              // [l][u][b]
__device__ __align__(128) float g_hf[4 * BH];             // [par*2+l][u][b]
__device__ unsigned g_bar_arrive;
__device__ unsigned g_bar_gen;

// ---------------- PTX helpers ----------------
__device__ __forceinline__ uint32_t smem_u32(const void* p) {
    uint32_t a;
    asm("{ .reg .u64 t; cvta.to.shared.u64 t, %1; cvt.u32.u64 %0, t; }"
        : "=r"(a) : "l"(p));
    return a;
}
__device__ __forceinline__ void cpa16(uint32_t s, const void* g) {
    asm volatile("cp.async.cg.shared.global [%0], [%1], 16;" :: "r"(s), "l"(g));
}
__device__ __forceinline__ void cpa_commit() {
    asm volatile("cp.async.commit_group;" ::: "memory");
}
__device__ __forceinline__ void cpa_wait1() {
    asm volatile("cp.async.wait_group 1;" ::: "memory");
}
__device__ __forceinline__ void cpa_wait0() {
    asm volatile("cp.async.wait_group 0;" ::: "memory");
}
__device__ __forceinline__ void ldsm4(uint32_t a, uint32_t& r0, uint32_t& r1,
                                      uint32_t& r2, uint32_t& r3) {
    asm volatile("ldmatrix.sync.aligned.m8n8.x4.shared.b16 {%0,%1,%2,%3}, [%4];"
                 : "=r"(r0), "=r"(r1), "=r"(r2), "=r"(r3) : "r"(a));
}
__device__ __forceinline__ void ldsm4t(uint32_t a, uint32_t& r0, uint32_t& r1,
                                       uint32_t& r2, uint32_t& r3) {
    asm volatile("ldmatrix.sync.aligned.m8n8.x4.trans.shared.b16 {%0,%1,%2,%3}, [%4];"
                 : "=r"(r0), "=r"(r1), "=r"(r2), "=r"(r3) : "r"(a));
}
__device__ __forceinline__ void mma16816(float* c, const uint32_t* a,
                                         uint32_t b0, uint32_t b1) {
    asm volatile("mma.sync.aligned.m16n8k16.row.col.f32.bf16.bf16.f32 "
                 "{%0,%1,%2,%3}, {%4,%5,%6,%7}, {%8,%9}, {%0,%1,%2,%3};"
                 : "+f"(c[0]), "+f"(c[1]), "+f"(c[2]), "+f"(c[3])
                 : "r"(a[0]), "r"(a[1]), "r"(a[2]), "r"(a[3]), "r"(b0), "r"(b1));
}
__device__ __forceinline__ float sigmoidf_(float x) { return 1.0f / (1.0f + expf(-x)); }
__device__ __forceinline__ void split1(float v, __nv_bfloat16& h, __nv_bfloat16& l) {
    h = __float2bfloat16_rn(v);
    l = __float2bfloat16_rn(v - __bfloat162float(h));
}
__device__ __forceinline__ uint32_t swz(uint32_t off) {
    return off ^ ((off >> 3) & 0x70);
}

// ---------------- grid barrier (all 128 blocks resident) ----------------
__device__ __forceinline__ void grid_barrier() {
    __syncthreads();
    if (threadIdx.x == 0) {
        __threadfence();
        unsigned gen = *((volatile unsigned*)&g_bar_gen);
        if (atomicAdd(&g_bar_arrive, 1u) == NBLK - 1) {
            g_bar_arrive = 0;
            __threadfence();
            atomicAdd(&g_bar_gen, 1u);
        } else {
            while (*((volatile unsigned*)&g_bar_gen) == gen) { __nanosleep(20); }
        }
        __threadfence();
    }
    __syncthreads();
}

// ---------------- persistent kernel ----------------
__global__ void __launch_bounds__(NTHR, 1)
lstm_hmma(const float* __restrict__ input,   // [512,64,1024]
          const float* __restrict__ h0,      // [2,64,1024]
          const float* __restrict__ c0,      // [2,64,1024]
          const float* __restrict__ W,       // [2,2048,4096]
          const float* __restrict__ bias,    // [2,4096]
          float* __restrict__ out)
{
    extern __shared__ __align__(1024) char dsm[];
    const uint32_t sbase = smem_u32(dsm);

    __shared__ float s_tr[32][33];
    __shared__ float s_hn[8][64];

    const int tid  = threadIdx.x;
    const int wid  = tid >> 5;
    const int lane = tid & 31;
    const int bid  = blockIdx.x;
    const int gid  = bid * NTHR + tid;
    const int cg   = bid & 31;        // M tile: rows [cg*128, +128)
    const int ks   = bid >> 5;        // K slice: [ks*512, +512)
    const int m0   = cg * 128;
    const int u0   = bid * 8;         // cell-owned units
    const int mw   = wid * 16;        // warp M strip within tile

    // ======== phase 0a: x transpose [t][b][u] -> [t][u][b] + bf16 split ====
    for (int tile = bid; tile < SEQ * 64; tile += NBLK) {
        const int t  = tile >> 6;
        const int ut = (tile >> 1) & 31;
        const int bt = tile & 1;
        const int ub = ut * 32, bb = bt * 32;
#pragma unroll
        for (int it = 0; it < 4; it++) {
            int r = (tid >> 5) + it * 8, c = tid & 31;
            s_tr[r][c] = input[((size_t)t * 64 + bb + r) * HID + ub + c];
        }
        __syncthreads();
#pragma unroll
        for (int it = 0; it < 4; it++) {
            int i = (tid >> 5) + it * 8, j = tid & 31;
            __nv_bfloat16 hv, lv;
            split1(s_tr[j][i], hv, lv);
            size_t dst = ((size_t)t * HID + ub + i) * 64 + bb + j;
            g_xhi[dst] = hv;
            g_xlo[dst] = lv;
        }
        __syncthreads();
    }
    // ======== phase 0b: W transpose + gate-permute + split ========
    // Wt[l][p][k] = W[l][k][n], p = ((n&1023)<<2) | (n>>10)
    for (int tile = bid; tile < 2 * 64 * 128; tile += NBLK) {
        const int l  = tile >> 13;
        const int kt = (tile & 8191) >> 7;
        const int nt = tile & 127;
        const int k0 = kt * 32, n0 = nt * 32;
#pragma unroll
        for (int r = 0; r < 4; r++) {
            int kk = (tid >> 5) + r * 8;
            s_tr[kk][lane] = W[((size_t)l * KTOT + k0 + kk) * NOUT + n0 + lane];
        }
        __syncthreads();
#pragma unroll
        for (int r = 0; r < 4; r++) {
            int j = (tid >> 5) + r * 8;
            int n = n0 + j;
            int p = ((n & 1023) << 2) | (n >> 10);
            __nv_bfloat16 hv, lv;
            split1(s_tr[lane][j], hv, lv);
            size_t dst = ((size_t)l * NOUT + p) * KTOT + k0 + lane;
            g_wthi[dst] = hv;
            g_wtlo[dst] = lv;
        }
        __syncthreads();
    }
    // ======== phase 0c: seed h (transposed, split) and c (transposed) =====
    for (int tile = bid; tile < 256; tile += NBLK) {
        const int kind = tile >> 7;
        const int rest = tile & 127;
        const int l  = rest >> 6;
        const int ut = (rest >> 1) & 31;
        const int bt = rest & 1;
        const int ub = ut * 32, bb = bt * 32;
        const float* src = (kind == 0) ? h0 : c0;
#pragma unroll
        for (int it = 0; it < 4; it++) {
            int r = (tid >> 5) + it * 8, c = tid & 31;
            s_tr[r][c] = src[((size_t)l * 64 + bb + r) * HID + ub + c];
        }
        __syncthreads();
#pragma unroll
        for (int it = 0; it < 4; it++) {
            int i = (tid >> 5) + it * 8, j = tid & 31;
            float v = s_tr[j][i];
            if (kind == 0) {
                __nv_bfloat16 hv, lv;
                split1(v, hv, lv);
                size_t dst = (size_t)l * BH + (size_t)(ub + i) * 64 + bb + j;
                g_hhi[dst] = hv;
                g_hlo[dst] = lv;
            } else {
                g_c[(size_t)l * BH + (size_t)(ub + i) * 64 + bb + j] = v;
            }
        }
        __syncthreads();
    }
    grid_barrier();

    // ---- lane-constant ldmatrix row bases + swizzle XORs ----
    // swz(row*128 + col) == row*128 + (col ^ ((row&7)*16))  for col < 128
    const int q  = lane >> 3, r8 = lane & 7;
    const int rowA = mw + r8 + (q & 1) * 8;           // 0..127 (A: [m][k])
    const uint32_t baseA = (uint32_t)rowA * 128;
    const uint32_t xorA  = (uint32_t)(rowA & 7) * 16;
    const int rowB = (q & 1) * 8 + r8;                // 0..15  (B: [k][b])
    const uint32_t baseB = (uint32_t)rowB * 128;
    const uint32_t xorB  = (uint32_t)(rowB & 7) * 16; // rowB advances by 16 per kk: &7 invariant
    const uint32_t colq  = (uint32_t)(q >> 1) * 16;

    // ======== main recurrence ========
    for (int t = 0; t < SEQ; t++) {
        const int pin  = t & 1;
        const int pout = pin ^ 1;
#pragma unroll 1
        for (int l = 0; l < 2; l++) {
            const __nv_bfloat16* Wh = g_wthi + ((size_t)l * NOUT + m0) * KTOT + ks * KSL;
            const __nv_bfloat16* Wo = g_wtlo + ((size_t)l * NOUT + m0) * KTOT + ks * KSL;
            const __nv_bfloat16 *Bh, *Bl;
            if (l == 0) {
                if (ks < 2) {
                    Bh = g_xhi + ((size_t)t * HID + ks * KSL) * 64;
                    Bl = g_xlo + ((size_t)t * HID + ks * KSL) * 64;
                } else {
                    Bh = g_hhi + (size_t)(pin * 2 + 0) * BH + (size_t)(ks - 2) * KSL * 64;
                    Bl = g_hlo + (size_t)(pin * 2 + 0) * BH + (size_t)(ks - 2) * KSL * 64;
                }
            } else {
                if (ks < 2) {
                    Bh = g_hhi + (size_t)(pout * 2 + 0) * BH + (size_t)ks * KSL * 64;
                    Bl = g_hlo + (size_t)(pout * 2 + 0) * BH + (size_t)ks * KSL * 64;
                } else {
                    Bh = g_hhi + (size_t)(pin * 2 + 1) * BH + (size_t)(ks - 2) * KSL * 64;
                    Bl = g_hlo + (size_t)(pin * 2 + 1) * BH + (size_t)(ks - 2) * KSL * 64;
                }
            }

            float acc[8][4];
#pragma unroll
            for (int i = 0; i < 8; i++)
#pragma unroll
                for (int j = 0; j < 4; j++) acc[i][j] = 0.0f;

            // issue chunk 0
            {
                const uint32_t st = sbase;
#pragma unroll
                for (int it = 0; it < 4; it++) {
                    int idx = tid + it * 256;
                    uint32_t off = swz((idx >> 3) * 128 + (idx & 7) * 16);
                    size_t go = (size_t)(idx >> 3) * KTOT + (idx & 7) * 8;
                    cpa16(st + off, Wh + go);
                    cpa16(st + 16384 + off, Wo + go);
                }
#pragma unroll
                for (int it = 0; it < 2; it++) {
                    int idx = tid + it * 256;
                    uint32_t off = swz((idx >> 3) * 128 + (idx & 7) * 16);
                    size_t go = (size_t)idx * 8;
                    cpa16(st + 32768 + off, Bh + go);
                    cpa16(st + 40960 + off, Bl + go);
                }
                cpa_commit();
            }

            for (int ch = 0; ch < NCHK; ch++) {
                if (ch < NCHK - 1) {   // issue chunk ch+1 into other buffer
                    const uint32_t st = sbase + ((ch + 1) & 1) * STGB;
                    const int kc = (ch + 1) * CHK;
#pragma unroll
                    for (int it = 0; it < 4; it++) {
                        int idx = tid + it * 256;
                        uint32_t off = swz((idx >> 3) * 128 + (idx & 7) * 16);
                        size_t go = (size_t)(idx >> 3) * KTOT + kc + (idx & 7) * 8;
                        cpa16(st + off, Wh + go);
                        cpa16(st + 16384 + off, Wo + go);
                    }
#pragma unroll
                    for (int it = 0; it < 2; it++) {
                        int idx = tid + it * 256;
                        uint32_t off = swz((idx >> 3) * 128 + (idx & 7) * 16);
                        size_t go = (size_t)(kc * 64) + (size_t)idx * 8;
                        cpa16(st + 32768 + off, Bh + go);
                        cpa16(st + 40960 + off, Bl + go);
                    }
                    cpa_commit();
                    cpa_wait1();
                } else {
                    cpa_wait0();
                }
                __syncthreads();

                // ---- compute chunk ch ----
                const uint32_t st = sbase + (ch & 1) * STGB;
#pragma unroll
                for (int kk = 0; kk < 4; kk++) {
                    const uint32_t aoff = baseA + ((colq + kk * 32) ^ xorA);
                    uint32_t ahi[4], alo[4];
                    ldsm4(st + aoff, ahi[0], ahi[1], ahi[2], ahi[3]);
                    ldsm4(st + 16384 + aoff, alo[0], alo[1], alo[2], alo[3]);
#pragma unroll
                    for (int p = 0; p < 4; p++) {
                        const uint32_t boff = baseB + (uint32_t)kk * 2048
                                            + ((colq + p * 32) ^ xorB);
                        uint32_t bh[4], bl[4];
                        ldsm4t(st + 32768 + boff, bh[0], bh[1], bh[2], bh[3]);
                        ldsm4t(st + 40960 + boff, bl[0], bl[1], bl[2], bl[3]);
                        mma16816(acc[2 * p],     ahi, bh[0], bh[1]);
                        mma16816(acc[2 * p],     ahi, bl[0], bl[1]);
                        mma16816(acc[2 * p],     alo, bh[0], bh[1]);
                        mma16816(acc[2 * p + 1], ahi, bh[2], bh[3]);
                        mma16816(acc[2 * p + 1], ahi, bl[2], bl[3]);
                        mma16816(acc[2 * p + 1], alo, bh[2], bh[3]);
                    }
                }
                __syncthreads();
            }

            // ---- epilogue: acc -> split-K partials ----
            {
                const int g  = lane >> 2;
                const int tt = lane & 3;
                float* base = g_partial + ((size_t)ks * NOUT + m0 + mw) * 64;
#pragma unroll
                for (int nt = 0; nt < 8; nt++) {
                    *reinterpret_cast<float2*>(base + (size_t)g * 64 + nt * 8 + 2 * tt) =
                        make_float2(acc[nt][0], acc[nt][1]);
                    *reinterpret_cast<float2*>(base + (size_t)(g + 8) * 64 + nt * 8 + 2 * tt) =
                        make_float2(acc[nt][2], acc[nt][3]);
                }
            }
            grid_barrier();

            // ---- cell phase: 8 units x 64 batches per CTA ----
            {
                const int b = tid & 63;
#pragma unroll
                for (int it2 = 0; it2 < 2; it2++) {
                    const int ul = (tid >> 6) + it2 * 4;
                    const int u = u0 + ul;
                    float gv[4];
#pragma unroll
                    for (int gate = 0; gate < 4; gate++) {
                        const int p = 4 * u + gate;
                        float s = bias[(size_t)l * NOUT + gate * 1024 + u];
#pragma unroll
                        for (int ksi = 0; ksi < NKS; ksi++)
                            s += g_partial[((size_t)ksi * NOUT + p) * 64 + b];
                        gv[gate] = s;
                    }
                    const size_t cidx = (size_t)l * BH + (size_t)u * 64 + b;
                    const float gi = sigmoidf_(gv[0]);
                    const float gj = tanhf(gv[1]);
                    const float gf = sigmoidf_(gv[2]);
                    const float go = sigmoidf_(gv[3]);
                    const float cn = g_c[cidx] * gf + gi * gj;
                    g_c[cidx] = cn;
                    const float hn = tanhf(cn) * go;
                    const size_t hidx = (size_t)(pout * 2 + l) * BH + (size_t)u * 64 + b;
                    g_hf[hidx] = hn;
                    __nv_bfloat16 hv, lv;
                    split1(hn, hv, lv);
                    g_hhi[hidx] = hv;
                    g_hlo[hidx] = lv;
                    s_hn[ul][b] = hn;
                }
                __syncthreads();
                if (l == 1 && tid < 64) {
                    const int b2 = tid;
                    float* op = out + (size_t)t * BH + (size_t)b2 * HID + u0;
                    reinterpret_cast<float4*>(op)[0] =
                        make_float4(s_hn[0][b2], s_hn[1][b2], s_hn[2][b2], s_hn[3][b2]);
                    reinterpret_cast<float4*>(op)[1] =
                        make_float4(s_hn[4][b2], s_hn[5][b2], s_hn[6][b2], s_hn[7][b2]);
                }
            }
            grid_barrier();
        }
    }

    // ======== tail: last_hidden (parity 0) + last_cell, de-transpose ======
    for (int i = gid; i < 2 * BH; i += GTH) {
        int l = i >> 16, rr = i & 65535, b = rr >> 10, u = rr & 1023;
        out[(size_t)SEQ * BH + i] = g_hf[(size_t)l * BH + (size_t)u * 64 + b];
        out[(size_t)SEQ * BH + 2 * BH + i] = g_c[(size_t)l * BH + (size_t)u * 64 + b];
    }
}

// ---------------- launch: ONE graph node ----------------
extern "C" void kernel_launch(void* const* d_in, const int* in_sizes, int n_in,
                              void* d_out, int out_size) {
    const float* input = (const float*)d_in[0];
    const float* h0    = (const float*)d_in[1];
    const float* c0    = (const float*)d_in[2];
    const float* W     = (const float*)d_in[3];
    const float* bias  = (const float*)d_in[4];
    float* out = (float*)d_out;

    cudaFuncSetAttribute(lstm_hmma, cudaFuncAttributeMaxDynamicSharedMemorySize, DSMEM);
    lstm_hmma<<<NBLK, NTHR, DSMEM>>>(input, h0, c0, W, bias, out);
}